// round 10
// baseline (speedup 1.0000x reference)
#include <cuda_runtime.h>
#include <cuda_fp16.h>
#include <math.h>
#include <cstdint>

#define BB 128
#define AA 512
#define RR 512
#define OUTN 10000
#define BR (BB*RR)
#define BA (BB*AA)
#define LW 2097152
#define LB 4096

// big HMMA GEMM tiling: 128x128, 1-term: stage = A 16K + W 16K, 3-deep pipeline
#define MT 128
#define NT 128
#define NSTAGES 8
#define STAGE_BYTES 32768

// ---------------- scratch (device globals; no allocations) ----------------
__device__ __half g_v1h[(size_t)BB*AA*AA];   // 67 MB, fp16 v1 (+bias)
__device__ float g_spart[2*8*BA];
__device__ float g_w0[BA];
__device__ float g_w1[BA];
__device__ float g_hhred[2*BA];
__device__ float g_hhpart[4*2*BA];
__device__ float g_h2a1part[4*BA];
__device__ float g_sums4[4*BB*4096];
__device__ float g_nexth[BR];
__device__ float g_scores[BA];
__device__ float g_logits2[(size_t)2*BB*OUTN];
// fp16 operands
__device__ __half g_att_h[(size_t)BB*AA*RR];
__device__ __half g_w0_h[AA*RR];
__device__ __half g_w1_h[AA*RR];
__device__ __half g_h2aw_h[AA*RR];
__device__ __half g_h2a1w_h[AA*RR];
__device__ __half g_i2h_h[2*LW];
__device__ __half g_h2h_h[2*LW];
__device__ __half g_a2h_h[2*LW];
__device__ __half g_proj_hi[OUTN*RR];
__device__ __half g_proj_lo[OUTN*RR];
__device__ __half g_x_h[BR];
__device__ __half g_h01_h[2*BR];
__device__ __half g_xt_h[BR];
__device__ __half g_nh_h[BR];
__device__ __half g_th_h[BR];
__device__ __half g_ar_h[2*BR];

// ---------------- PTX helpers ----------------
__device__ __forceinline__ uint32_t smem_u32(const void* p){
    uint32_t a;
    asm("{ .reg .u64 t; cvta.to.shared.u64 t, %1; cvt.u32.u64 %0, t; }" : "=r"(a) : "l"(p));
    return a;
}
__device__ __forceinline__ void cp16(uint32_t dst, const void* src){
    asm volatile("cp.async.cg.shared.global [%0], [%1], 16;\n" :: "r"(dst), "l"(src));
}
__device__ __forceinline__ void cp16z(uint32_t dst, const void* src, bool ok){
    int sz = ok ? 16 : 0;
    asm volatile("cp.async.cg.shared.global [%0], [%1], 16, %2;\n" :: "r"(dst), "l"(src), "r"(sz));
}
#define CP_COMMIT()  asm volatile("cp.async.commit_group;\n" ::: "memory")
#define CP_WAIT0()   asm volatile("cp.async.wait_group 0;\n" ::: "memory")
#define CP_WAIT1()   asm volatile("cp.async.wait_group 1;\n" ::: "memory")

#define SWZ(off) ((off) ^ (((off) >> 3) & 0x70))

__device__ __forceinline__ void ldsm_x4(uint32_t& r0, uint32_t& r1, uint32_t& r2, uint32_t& r3, uint32_t addr){
    asm volatile("ldmatrix.sync.aligned.m8n8.x4.shared.b16 {%0,%1,%2,%3}, [%4];"
        : "=r"(r0), "=r"(r1), "=r"(r2), "=r"(r3) : "r"(addr));
}
__device__ __forceinline__ void mma16816(float* c, const uint32_t* a, const uint32_t* b){
    asm volatile(
        "mma.sync.aligned.m16n8k16.row.col.f32.f16.f16.f32 "
        "{%0,%1,%2,%3}, {%4,%5,%6,%7}, {%8,%9}, {%0,%1,%2,%3};"
        : "+f"(c[0]), "+f"(c[1]), "+f"(c[2]), "+f"(c[3])
        : "r"(a[0]), "r"(a[1]), "r"(a[2]), "r"(a[3]), "r"(b[0]), "r"(b[1]));
}

// ---------------- fp32 -> fp16 single (big arrays) ----------------
__global__ void tohalf_kernel(const float* __restrict__ in, __half* __restrict__ out, size_t n4)
{
    size_t i = (size_t)blockIdx.x*blockDim.x + threadIdx.x;
    if (i >= n4) return;
    float4 x = ((const float4*)in)[i];
    __half h[4] = { __float2half_rn(x.x), __float2half_rn(x.y),
                    __float2half_rn(x.z), __float2half_rn(x.w) };
    ((uint2*)out)[i] = *(uint2*)h;
}

// ---------------- fp32 -> fp16, up to 4 equal-size segments in one launch ----------------
__global__ void tohalf_multi_kernel(const float* __restrict__ s0, __half* __restrict__ d0,
                                    const float* __restrict__ s1, __half* __restrict__ d1,
                                    const float* __restrict__ s2, __half* __restrict__ d2,
                                    const float* __restrict__ s3, __half* __restrict__ d3,
                                    int nseg, size_t n4each)
{
    size_t gi = (size_t)blockIdx.x*blockDim.x + threadIdx.x;
    int seg = (int)(gi / n4each);
    if (seg >= nseg) return;
    size_t i = gi - (size_t)seg * n4each;
    const float* in = seg==0 ? s0 : seg==1 ? s1 : seg==2 ? s2 : s3;
    __half* out     = seg==0 ? d0 : seg==1 ? d1 : seg==2 ? d2 : d3;
    float4 x = ((const float4*)in)[i];
    __half h[4] = { __float2half_rn(x.x), __float2half_rn(x.y),
                    __float2half_rn(x.z), __float2half_rn(x.w) };
    ((uint2*)out)[i] = *(uint2*)h;
}

// ---------------- fp32 -> fp16 hi/lo split (proj only) ----------------
__global__ void splith_kernel(const float* __restrict__ in,
                              __half* __restrict__ hi, __half* __restrict__ lo, size_t n4)
{
    size_t i = (size_t)blockIdx.x*blockDim.x + threadIdx.x;
    if (i >= n4) return;
    float4 x = ((const float4*)in)[i];
    float xv[4] = {x.x, x.y, x.z, x.w};
    __half h[4], l[4];
    #pragma unroll
    for (int j=0;j<4;j++){
        h[j] = __float2half_rn(xv[j]);
        l[j] = __float2half_rn(xv[j] - __half2float(h[j]));
    }
    ((uint2*)hi)[i] = *(uint2*)h;
    ((uint2*)lo)[i] = *(uint2*)l;
}

// =====================================================================
// big HMMA fp16 1-term GEMM over att: C = att @ W^T
// 3-deep cp.async pipeline, ONE barrier per stage. 2 CTAs/SM.
// grid.x = (nt4<<1)|set (8), grid.y = mtile (512)
// =====================================================================
__global__ __launch_bounds__(256, 2)
void hmma_gemm_kernel(const __half* __restrict__ Ah,
                      const __half* __restrict__ W0h, const __half* __restrict__ W1h,
                      const float* __restrict__ ba0, const float* __restrict__ ba1,
                      const float* __restrict__ wd0,
                      const float* __restrict__ hh0, const float* __restrict__ hh1,
                      __half* __restrict__ v1out,
                      float* __restrict__ sp0, float* __restrict__ sp1)
{
    extern __shared__ char dsm[];
    const int tid  = threadIdx.x;
    const int wid  = tid >> 5;
    const int lane = tid & 31;
    const int grp  = lane >> 2;
    const int tid4 = lane & 3;
    const int set  = blockIdx.x & 1;
    const int nt4  = blockIdx.x >> 1;
    const int mBase = blockIdx.y * MT;
    const int nBase4 = nt4 * NT;
    const int wm = wid >> 1;
    const int wn = wid & 1;

    const __half* Wh = set ? W1h : W0h;
    const float* bias = set ? ba1 : ba0;

    const uint32_t sbase = smem_u32(dsm);

    // ldmatrix per-lane constants
    const int l15 = lane & 15;
    const uint32_t Cx = ((uint32_t)(lane >> 4) * 16) ^ ((uint32_t)(lane & 7) << 4);
    const uint32_t offA0 = (uint32_t)(wm*32 + l15) * 128;
    const uint32_t offA1 = offA0 + 2048;
    uint32_t offB[4];
    #pragma unroll
    for (int p = 0; p < 4; p++) offB[p] = (uint32_t)(wn*64 + p*16 + l15) * 128;

    float acc[2][8][4];
    #pragma unroll
    for (int mt=0;mt<2;mt++)
        #pragma unroll
        for (int nt=0;nt<8;nt++)
            #pragma unroll
            for (int q=0;q<4;q++) acc[mt][nt][q]=0.f;

    auto load_stage = [&](int s, int buf){
        const uint32_t base = sbase + buf * STAGE_BYTES;
        const int kOff = s * 64;
        #pragma unroll
        for (int i = 0; i < 4; i++){              // A: 1024 chunks
            int idx = tid + i * 256;
            int r = idx >> 3;
            int ch = idx & 7;
            const __half* src = Ah + (size_t)(mBase + r) * RR + kOff + ch * 8;
            cp16(base + SWZ(r * 128 + ch * 16), src);
        }
        #pragma unroll
        for (int i = 0; i < 4; i++){              // B: 1024 chunks
            int idx = tid + i * 256;
            int r = idx >> 3;
            int ch = idx & 7;
            const __half* src = Wh + (size_t)(nBase4 + r) * RR + kOff + ch * 8;
            cp16(base + 16384 + SWZ(r * 128 + ch * 16), src);
        }
        CP_COMMIT();
    };

    load_stage(0, 0);
    load_stage(1, 1);

    for (int s = 0; s < NSTAGES; s++){
        if (s + 1 < NSTAGES){ CP_WAIT1(); } else { CP_WAIT0(); }
        __syncthreads();     // buf[s%3] ready; all warps done computing buf[(s+2)%3]'s old contents

        const uint32_t sA = sbase + (s % 3) * STAGE_BYTES;
        const uint32_t sB = sA + 16384;
        #pragma unroll
        for (int k16 = 0; k16 < 4; k16++){
            const uint32_t ko = ((uint32_t)k16 * 32) ^ Cx;
            uint32_t a0[4], a1[4];
            ldsm_x4(a0[0], a0[1], a0[2], a0[3], sA + offA0 + ko);
            ldsm_x4(a1[0], a1[1], a1[2], a1[3], sA + offA1 + ko);
            #pragma unroll
            for (int p = 0; p < 4; p++){
                uint32_t b0, b1, b2, b3;
                ldsm_x4(b0, b1, b2, b3, sB + offB[p] + ko);
                uint32_t be[2] = {b0, b2};
                uint32_t bo[2] = {b1, b3};
                mma16816(acc[0][2*p],   a0, be);
                mma16816(acc[0][2*p+1], a0, bo);
                mma16816(acc[1][2*p],   a1, be);
                mma16816(acc[1][2*p+1], a1, bo);
            }
        }
        if (s + 2 < NSTAGES) load_stage(s + 2, (s + 2) % 3);
    }

    if (set == 1){
        #pragma unroll
        for (int mt = 0; mt < 2; mt++){
            #pragma unroll
            for (int rh = 0; rh < 2; rh++){
                int m = mBase + wm*32 + mt*16 + rh*8 + grp;
                __half* dst = v1out + (size_t)m * AA;
                #pragma unroll
                for (int nt = 0; nt < 8; nt++){
                    int n0 = nBase4 + wn*64 + nt*8 + tid4*2;
                    __half2 h2 = __floats2half2_rn(acc[mt][nt][rh*2+0] + bias[n0],
                                                   acc[mt][nt][rh*2+1] + bias[n0+1]);
                    *(__half2*)(dst + n0) = h2;
                }
            }
        }
    } else {
        const int part = nt4*2 + wn;
        #pragma unroll
        for (int mt = 0; mt < 2; mt++){
            #pragma unroll
            for (int rh = 0; rh < 2; rh++){
                int m = mBase + wm*32 + mt*16 + rh*8 + grp;
                float h0 = hh0[m], h1 = hh1[m];
                float p0 = 0.f, p1 = 0.f;
                #pragma unroll
                for (int nt = 0; nt < 8; nt++){
                    int n0 = nBase4 + wn*64 + nt*8 + tid4*2;
                    float v0 = acc[mt][nt][rh*2+0] + bias[n0];
                    float v1v = acc[mt][nt][rh*2+1] + bias[n0+1];
                    float wv0 = wd0[n0], wv1 = wd0[n0+1];
                    p0 += tanhf(v0 + h0)*wv0 + tanhf(v1v + h0)*wv1;
                    p1 += tanhf(v0 + h1)*wv0 + tanhf(v1v + h1)*wv1;
                }
                p0 += __shfl_down_sync(0xffffffffu, p0, 2, 4);
                p0 += __shfl_down_sync(0xffffffffu, p0, 1, 4);
                p1 += __shfl_down_sync(0xffffffffu, p1, 2, 4);
                p1 += __shfl_down_sync(0xffffffffu, p1, 1, 4);
                if (tid4 == 0){
                    sp0[(size_t)part*BA + m] = p0;
                    sp1[(size_t)part*BA + m] = p1;
                }
            }
        }
    }
}

// =====================================================================
// Generic fp16 GEMM, 128x64 tile, multi-source K, K-split, 3-deep pipeline.
// =====================================================================
template<int NSRC, bool TWOTERM>
__global__ __launch_bounds__(256, 2)
void hgemm_kernel(const __half* __restrict__ Xh0,
                  const __half* __restrict__ Whi0, const __half* __restrict__ Wlo0,
                  const __half* __restrict__ Xh1,
                  const __half* __restrict__ Whi1, const __half* __restrict__ Wlo1,
                  const __half* __restrict__ Xh2,
                  const __half* __restrict__ Whi2, const __half* __restrict__ Wlo2,
                  float* __restrict__ out, int Nreal, int kStride)
{
    constexpr uint32_t STG = TWOTERM ? 32768 : 24576;
    extern __shared__ char dsm[];
    const int tid  = threadIdx.x;
    const int wid  = tid >> 5;
    const int lane = tid & 31;
    const int grp  = lane >> 2;
    const int tid4 = lane & 3;
    const int nBase = blockIdx.x * 64;
    const int kIdx  = blockIdx.y;
    const int mBase = blockIdx.z * 128;
    const int wm = wid >> 1;
    const int wn = wid & 1;
    const uint32_t sbase = smem_u32(dsm);

    const int spc  = (NSRC * 8) / gridDim.y;
    const int sBeg = kIdx * spc;

    const int l15 = lane & 15;
    const uint32_t Cx = ((uint32_t)(lane >> 4) * 16) ^ ((uint32_t)(lane & 7) << 4);
    const uint32_t offA0 = (uint32_t)(wm*32 + l15) * 128;
    const uint32_t offA1 = offA0 + 2048;
    uint32_t offB[2];
    #pragma unroll
    for (int p = 0; p < 2; p++) offB[p] = (uint32_t)(wn*32 + p*16 + l15) * 128;

    float acc[2][4][4];
    #pragma unroll
    for (int mt=0;mt<2;mt++)
        #pragma unroll
        for (int nt=0;nt<4;nt++)
            #pragma unroll
            for (int q=0;q<4;q++) acc[mt][nt][q]=0.f;

    auto load_stage = [&](int s, int buf){
        const uint32_t base = sbase + buf * STG;
        const int src = s >> 3;
        const int kOff = (s & 7) * 64;
        const __half *xh, *wh, *wl;
        if (NSRC == 1 || src == 0){ xh=Xh0; wh=Whi0; wl=Wlo0; }
        else if (src == 1){ xh=Xh1; wh=Whi1; wl=Wlo1; }
        else { xh=Xh2; wh=Whi2; wl=Wlo2; }
        #pragma unroll
        for (int i = 0; i < 4; i++){              // A: 1024 chunks
            int idx = tid + i * 256;
            int r = idx >> 3;
            int ch = idx & 7;
            const __half* src_p = xh + (size_t)(mBase + r) * 512 + kOff + ch * 8;
            cp16(base + SWZ(r * 128 + ch * 16), src_p);
        }
        #pragma unroll
        for (int i = 0; i < (TWOTERM ? 4 : 2); i++){  // B chunks
            int idx = tid + i * 256;
            int half = idx >> 9;
            int r = (idx >> 3) & 63;
            int ch = idx & 7;
            bool ok = (nBase + r) < Nreal;
            const __half* src_p = ((TWOTERM && half) ? wl : wh) + (size_t)(nBase + r) * 512 + kOff + ch * 8;
            cp16z(base + 16384 + half * 8192 + SWZ(r * 128 + ch * 16), src_p, ok);
        }
        CP_COMMIT();
    };

    load_stage(sBeg, 0);
    if (spc > 1) load_stage(sBeg + 1, 1);

    for (int i = 0; i < spc; i++){
        if (i + 1 < spc){ CP_WAIT1(); } else { CP_WAIT0(); }
        __syncthreads();

        const uint32_t sA  = sbase + (i % 3) * STG;
        const uint32_t sBh = sA + 16384;
        const uint32_t sBl = sA + 24576;
        #pragma unroll
        for (int k16 = 0; k16 < 4; k16++){
            const uint32_t ko = ((uint32_t)k16 * 32) ^ Cx;
            uint32_t a0[4], a1[4];
            ldsm_x4(a0[0], a0[1], a0[2], a0[3], sA + offA0 + ko);
            ldsm_x4(a1[0], a1[1], a1[2], a1[3], sA + offA1 + ko);
            #pragma unroll
            for (int p = 0; p < 2; p++){
                uint32_t b0, b1, b2, b3;
                ldsm_x4(b0, b1, b2, b3, sBh + offB[p] + ko);
                uint32_t be[2] = {b0, b2};
                uint32_t bo[2] = {b1, b3};
                mma16816(acc[0][2*p],   a0, be);
                mma16816(acc[0][2*p+1], a0, bo);
                mma16816(acc[1][2*p],   a1, be);
                mma16816(acc[1][2*p+1], a1, bo);
                if (TWOTERM){
                    ldsm_x4(b0, b1, b2, b3, sBl + offB[p] + ko);
                    uint32_t ce[2] = {b0, b2};
                    uint32_t co[2] = {b1, b3};
                    mma16816(acc[0][2*p],   a0, ce);
                    mma16816(acc[0][2*p+1], a0, co);
                    mma16816(acc[1][2*p],   a1, ce);
                    mma16816(acc[1][2*p+1], a1, co);
                }
            }
        }
        if (i + 2 < spc) load_stage(sBeg + i + 2, (i + 2) % 3);
    }

    float* obase = out + (size_t)kIdx * kStride;
    #pragma unroll
    for (int mt = 0; mt < 2; mt++){
        #pragma unroll
        for (int rh = 0; rh < 2; rh++){
            int m = mBase + wm*32 + mt*16 + rh*8 + grp;
            #pragma unroll
            for (int nt = 0; nt < 4; nt++){
                int n0 = nBase + wn*32 + nt*8 + tid4*2;
                if (n0 < Nreal){
                    float2 v2;
                    v2.x = acc[mt][nt][rh*2+0];
                    v2.y = acc[mt][nt][rh*2+1];
                    *(float2*)(obase + (size_t)m * Nreal + n0) = v2;
                }
            }
        }
    }
}

// ---------------- reduce partials + bias (biasN=512) ----------------
__global__ void reduce_bias_kernel(const float* __restrict__ in, const float* __restrict__ bias,
                                   float* __restrict__ out, int n, int parts, int pstride)
{
    int i = blockIdx.x*256 + threadIdx.x;
    if (i >= n) return;
    float s = bias[i & 511];
    for (int p = 0; p < parts; p++) s += in[(size_t)p*pstride + i];
    out[i] = s;
}

// ---------------- softmax over a (A=512), summing nparts partials ----------------
__global__ void softmax512_kernel(const float* __restrict__ in, float* __restrict__ out, int nparts)
{
    __shared__ float sm[8];
    int b = blockIdx.x, t = threadIdx.x;
    float v0=0.f, v1=0.f;
    for (int p=0;p<nparts;p++){
        const float* ip = in + (size_t)p*BA + (size_t)b*AA;
        v0 += ip[t]; v1 += ip[t+256];
    }
    float m = fmaxf(v0,v1);
    for (int o=16;o;o>>=1) m = fmaxf(m, __shfl_xor_sync(0xffffffffu,m,o));
    if ((t&31)==0) sm[t>>5]=m;
    __syncthreads();
    float M = sm[0];
    #pragma unroll
    for (int i=1;i<8;i++) M = fmaxf(M, sm[i]);
    __syncthreads();
    float e0=expf(v0-M), e1=expf(v1-M);
    float s = e0+e1;
    for (int o=16;o;o>>=1) s += __shfl_xor_sync(0xffffffffu,s,o);
    if ((t&31)==0) sm[t>>5]=s;
    __syncthreads();
    float S=0.f;
    #pragma unroll
    for (int i=0;i<8;i++) S += sm[i];
    float inv = 1.f/S;
    out[(size_t)b*AA + t]     = e0*inv;
    out[(size_t)b*AA + t+256] = e1*inv;
}

// ---------------- score scan over fp16 v1, fusing h2a1 partial-reduce ----------------
__global__ void v1_scores_kernel(const __half* __restrict__ v1, const float* __restrict__ parts,
                                 const float* __restrict__ hbias,
                                 const float* __restrict__ wd, float* __restrict__ scores)
{
    __shared__ float sm[4];
    int a = blockIdx.x, b = blockIdx.y, t = threadIdx.x;   // 128 threads
    size_t hidx = (size_t)b*AA + a;
    float h = hbias[a];
    #pragma unroll
    for (int p=0;p<4;p++) h += parts[(size_t)p*BA + hidx];
    uint2 u = ((const uint2*)(v1 + hidx*AA))[t];
    float2 f01 = __half22float2(*reinterpret_cast<__half2*>(&u.x));
    float2 f23 = __half22float2(*reinterpret_cast<__half2*>(&u.y));
    float4 w = ((const float4*)wd)[t];
    float s = tanhf(f01.x+h)*w.x + tanhf(f01.y+h)*w.y + tanhf(f23.x+h)*w.z + tanhf(f23.y+h)*w.w;
    for (int o=16;o;o>>=1) s += __shfl_xor_sync(0xffffffffu,s,o);
    if ((t&31)==0) sm[t>>5]=s;
    __syncthreads();
    if (t==0) scores[hidx] = sm[0]+sm[1]+sm[2]+sm[3];
}

// ---------------- att_res over fp16 att (+ fused fp16 converts) ----------------
template<bool DUAL, bool ADD>
__global__ void attres_kernel(const __half* __restrict__ att,
                              const float* __restrict__ w0, const float* __restrict__ w1,
                              const float* __restrict__ addv, const float* __restrict__ xadd,
                              float* __restrict__ out0,
                              __half* __restrict__ h0out, __half* __restrict__ h1out)
{
    __shared__ float sw0[AA];
    __shared__ float sw1[AA];
    int b = blockIdx.y;
    int r = blockIdx.x*256 + threadIdx.x;
    for (int a=threadIdx.x; a<AA; a+=256){
        sw0[a]=w0[(size_t)b*AA+a];
        if (DUAL) sw1[a]=w1[(size_t)b*AA+a];
    }
    __syncthreads();
    float acc0=0.f, acc1=0.f;
    const __half* ap = att + (size_t)b*AA*RR + r;
    #pragma unroll 8
    for (int a=0;a<AA;a++){
        float av = __half2float(ap[(size_t)a*RR]);
        acc0 = fmaf(sw0[a], av, acc0);
        if (DUAL) acc1 = fmaf(sw1[a], av, acc1);
    }
    size_t idx = (size_t)b*RR + r;
    if (ADD) acc0 += addv[idx];
    if (out0) out0[idx] = acc0;
    float e0 = xadd ? acc0 + xadd[idx] : acc0;
    h0out[idx] = __float2half_rn(e0);
    if (DUAL) h1out[idx] = __float2half_rn(acc1);
}

// ---------------- LSTM pointwise: sums 4 K-split partials + biases ----------------
__global__ void lstm_pw_kernel(const float* __restrict__ sums4,
                               const float* __restrict__ bi, const float* __restrict__ bh,
                               const float* __restrict__ ba,
                               const float* __restrict__ prev_c,
                               float* __restrict__ next_c, float* __restrict__ next_h,
                               __half* __restrict__ nh_h)
{
    int idx = blockIdx.x*256 + threadIdx.x;
    int b = idx >> 9, r = idx & 511;
    float pc = prev_c[idx];
    float cs=0.f, hs=0.f;
    #pragma unroll
    for (int p=0;p<2;p++){
        float g[4];
        #pragma unroll
        for (int gi=0; gi<4; gi++){
            int off = p*2048 + gi*512 + r;
            float s = bi[off] + bh[off] + ba[off];
            #pragma unroll
            for (int q=0;q<4;q++) s += sums4[(size_t)q*(BB*4096) + (size_t)b*4096 + off];
            g[gi] = s;
        }
        float ig = 1.f/(1.f+expf(-g[0]));
        float fg = 1.f/(1.f+expf(-g[1]));
        float og = 1.f/(1.f+expf(-g[2]));
        float tt = tanhf(g[3]);
        float c  = fg*pc + ig*tt;
        cs += c; hs += og*tanhf(c);
    }
    float nc = cs*0.5f, nh = hs*0.5f;
    next_c[idx] = nc;
    next_h[idx] = nh;
    nh_h[idx] = __float2half_rn(nh);
}

// ---------------- log_softmax: sums 2 proj partials + bias, smem-cached ----------------
__global__ void logsoftmax_kernel(const float* __restrict__ parts, const float* __restrict__ bias,
                                  float* __restrict__ out)
{
    __shared__ float sx[OUTN];
    __shared__ float sm[8];
    int b = blockIdx.x, t = threadIdx.x;
    const float* a0 = parts + (size_t)b*OUTN;
    const float* a1 = parts + (size_t)(BB + b)*OUTN;
    for (int i=t;i<OUTN;i+=256) sx[i] = a0[i] + a1[i] + bias[i];
    __syncthreads();
    float m = -3.4e38f;
    for (int i=t;i<OUTN;i+=256) m = fmaxf(m, sx[i]);
    for (int o=16;o;o>>=1) m = fmaxf(m, __shfl_xor_sync(0xffffffffu,m,o));
    if ((t&31)==0) sm[t>>5]=m;
    __syncthreads();
    float M = sm[0];
    #pragma unroll
    for (int i=1;i<8;i++) M = fmaxf(M, sm[i]);
    __syncthreads();
    float s=0.f;
    for (int i=t;i<OUTN;i+=256) s += expf(sx[i]-M);
    for (int o=16;o;o>>=1) s += __shfl_xor_sync(0xffffffffu,s,o);
    if ((t&31)==0) sm[t>>5]=s;
    __syncthreads();
    float S=0.f;
    #pragma unroll
    for (int i=0;i<8;i++) S += sm[i];
    float L = M + logf(S);
    for (int i=t;i<OUTN;i+=256) out[(size_t)b*OUTN+i] = sx[i]-L;
}

// =====================================================================
extern "C" void kernel_launch(void* const* d_in, const int* in_sizes, int n_in,
                              void* d_out, int out_size)
{
    const float* x      = (const float*)d_in[0];
    const float* att    = (const float*)d_in[1];
    const float* inputs = (const float*)d_in[2];
    const float* a2a_w  = (const float*)d_in[3];
    const float* a2a_b  = (const float*)d_in[4];
    const float* h2a_w  = (const float*)d_in[5];
    const float* h2a_b  = (const float*)d_in[6];
    const float* d2d_w  = (const float*)d_in[7];
    const float* a2a1_w = (const float*)d_in[9];
    const float* a2a1_b = (const float*)d_in[10];
    const float* h2a1_w = (const float*)d_in[11];
    const float* h2a1_b = (const float*)d_in[12];
    const float* d2d1_w = (const float*)d_in[13];
    const float* i2h_w  = (const float*)d_in[15];
    const float* i2h_b  = (const float*)d_in[16];
    const float* h2h_w  = (const float*)d_in[17];
    const float* h2h_b  = (const float*)d_in[18];
    const float* a2h_w  = (const float*)d_in[19];
    const float* a2h_b  = (const float*)d_in[20];
    const float* proj_w = (const float*)d_in[21];
    const float* proj_b = (const float*)d_in[22];
    float* out = (float*)d_out;

    float *spart, *w0p, *w1p, *hhredp, *hhpartp, *h2a1partp, *sums4p, *nexthp, *scoresp, *logits2p;
    __half* v1hp;
    cudaGetSymbolAddress((void**)&v1hp,     g_v1h);
    cudaGetSymbolAddress((void**)&spart,    g_spart);
    cudaGetSymbolAddress((void**)&w0p,      g_w0);
    cudaGetSymbolAddress((void**)&w1p,      g_w1);
    cudaGetSymbolAddress((void**)&hhredp,   g_hhred);
    cudaGetSymbolAddress((void**)&hhpartp,  g_hhpart);
    cudaGetSymbolAddress((void**)&h2a1partp,g_h2a1part);
    cudaGetSymbolAddress((void**)&sums4p,   g_sums4);
    cudaGetSymbolAddress((void**)&nexthp,   g_nexth);
    cudaGetSymbolAddress((void**)&scoresp,  g_scores);
    cudaGetSymbolAddress((void**)&logits2p, g_logits2);

    __half *ah,*w0h,*w1h,*h2awh,*h2a1wh,*i2hh,*h2hh,*a2hh,*projhi,*projlo;
    __half *xh,*h01h,*xth,*nhh,*thh,*arh;
    cudaGetSymbolAddress((void**)&ah, g_att_h);
    cudaGetSymbolAddress((void**)&w0h, g_w0_h);
    cudaGetSymbolAddress((void**)&w1h, g_w1_h);
    cudaGetSymbolAddress((void**)&h2awh, g_h2aw_h);
    cudaGetSymbolAddress((void**)&h2a1wh, g_h2a1w_h);
    cudaGetSymbolAddress((void**)&i2hh, g_i2h_h);
    cudaGetSymbolAddress((void**)&h2hh, g_h2h_h);
    cudaGetSymbolAddress((void**)&a2hh, g_a2h_h);
    cudaGetSymbolAddress((void**)&projhi, g_proj_hi);
    cudaGetSymbolAddress((void**)&projlo, g_proj_lo);
    cudaGetSymbolAddress((void**)&xh, g_x_h);
    cudaGetSymbolAddress((void**)&h01h, g_h01_h);
    cudaGetSymbolAddress((void**)&xth, g_xt_h);
    cudaGetSymbolAddress((void**)&nhh, g_nh_h);
    cudaGetSymbolAddress((void**)&thh, g_th_h);
    cudaGetSymbolAddress((void**)&arh, g_ar_h);

    const float* prev_c0 = inputs;
    const float* prev_h0 = inputs + 1*BR;
    const float* prev_c1 = inputs + 2*BR;
    const float* prev_h1 = inputs + 3*BR;

    float* sp0 = spart;
    float* sp1 = spart + (size_t)8*BA;

    cudaFuncSetAttribute(hmma_gemm_kernel, cudaFuncAttributeMaxDynamicSharedMemorySize, 3*STAGE_BYTES);
    cudaFuncSetAttribute((hgemm_kernel<1,false>), cudaFuncAttributeMaxDynamicSharedMemorySize, 3*24576);
    cudaFuncSetAttribute((hgemm_kernel<3,false>), cudaFuncAttributeMaxDynamicSharedMemorySize, 3*24576);
    cudaFuncSetAttribute((hgemm_kernel<1,true>),  cudaFuncAttributeMaxDynamicSharedMemorySize, 3*32768);

    // ---- converts (batched: 5 launches) ----
    {
        size_t n4 = (size_t)BB*AA*RR/4;
        tohalf_kernel<<<(unsigned)((n4+255)/256),256>>>(att, ah, n4);
        tohalf_multi_kernel<<<(4*65536+255)/256,256>>>(
            a2a_w, w0h, a2a1_w, w1h, h2a_w, h2awh, h2a1_w, h2a1wh, 4, 65536);
        tohalf_multi_kernel<<<(3*1048576+255)/256,256>>>(
            i2h_w, i2hh, h2h_w, h2hh, a2h_w, a2hh, 0, 0, 3, 1048576);
        tohalf_multi_kernel<<<(3*16384+255)/256,256>>>(
            x, xh, prev_h0, h01h, prev_h1, h01h+BR, 0, 0, 3, 16384);
        splith_kernel<<<5000,256>>>(proj_w, projhi, projlo, OUTN*RR/4);
    }

    // ---- hh for both prev-attends: M=256, N=512, K=512, ksplit=4 ----
    hgemm_kernel<1,false><<<dim3(8,4,2),256,3*24576>>>(
        h01h, h2awh, 0, 0,0,0, 0,0,0, hhpartp, AA, 2*BA);
    reduce_bias_kernel<<<(2*BA+255)/256,256>>>(hhpartp, h2a_b, hhredp, 2*BA, 4, 2*BA);

    // ---- big tensor GEMMs ----
    hmma_gemm_kernel<<<dim3(8,512),256,3*STAGE_BYTES>>>(
        ah, w0h, w1h, a2a_b, a2a1_b, d2d_w, hhredp, hhredp+BA, v1hp, sp0, sp1);

    softmax512_kernel<<<BB,256>>>(sp0, w0p, 8);
    softmax512_kernel<<<BB,256>>>(sp1, w1p, 8);

    // both prev att_res (fp16 att source)
    attres_kernel<true,false><<<dim3(2,BB),256>>>(ah, w0p, w1p, nullptr, nullptr,
        nullptr, arh, arh+BR);

    // ---- layer 0 ----
    hgemm_kernel<3,false><<<dim3(64,4,1),256,3*24576>>>(
        xh, i2hh, 0,
        h01h, h2hh, 0,
        arh, a2hh, 0,
        sums4p, 4096, BB*4096);
    lstm_pw_kernel<<<BR/256,256>>>(sums4p, i2h_b, h2h_b, a2h_b, prev_c0,
                                   out + 0, nexthp, nhh);

    hgemm_kernel<1,false><<<dim3(8,4,1),256,3*24576>>>(
        nhh, h2a1wh, 0, 0,0,0, 0,0,0, h2a1partp, AA, BA);
    v1_scores_kernel<<<dim3(AA,BB),128>>>(v1hp, h2a1partp, h2a1_b, d2d1_w, scoresp);
    softmax512_kernel<<<BB,256>>>(scoresp, w0p, 1);
    // top_h0 -> out+BR; xt = x + top_h0 -> fp16
    attres_kernel<false,true><<<dim3(2,BB),256>>>(ah, w0p, nullptr, nexthp, x,
        out + BR, xth, nullptr);

    // ---- layer 1 ----
    hgemm_kernel<3,false><<<dim3(64,4,1),256,3*24576>>>(
        xth, i2hh + LW, 0,
        h01h + BR, h2hh + LW, 0,
        arh + BR, a2hh + LW, 0,
        sums4p, 4096, BB*4096);
    lstm_pw_kernel<<<BR/256,256>>>(sums4p, i2h_b + LB, h2h_b + LB, a2h_b + LB, prev_c1,
                                   out + 2*BR, nexthp, nhh);

    hgemm_kernel<1,false><<<dim3(8,4,1),256,3*24576>>>(
        nhh, h2a1wh, 0, 0,0,0, 0,0,0, h2a1partp, AA, BA);
    v1_scores_kernel<<<dim3(AA,BB),128>>>(v1hp, h2a1partp, h2a1_b, d2d1_w, scoresp);
    softmax512_kernel<<<BB,256>>>(scoresp, w0p, 1);
    // top_h1 -> out+3BR and fp16 for proj
    attres_kernel<false,true><<<dim3(2,BB),256>>>(ah, w0p, nullptr, nexthp, nullptr,
        out + 3*BR, thh, nullptr);

    // ---- projection + log_softmax (2-term: logits are output-critical) ----
    hgemm_kernel<1,true><<<dim3(157,2,1),256,3*32768>>>(
        thh, projhi, projlo, 0,0,0, 0,0,0, logits2p, OUTN, BB*OUTN);
    logsoftmax_kernel<<<BB,256>>>(logits2p, proj_b, out + 4*BR);
}

// round 11
// speedup vs baseline: 1.0074x; 1.0074x over previous
#include <cuda_runtime.h>
#include <cuda_fp16.h>
#include <math.h>
#include <cstdint>

#define BB 128
#define AA 512
#define RR 512
#define OUTN 10000
#define BR (BB*RR)
#define BA (BB*AA)
#define LW 2097152
#define LB 4096

// big HMMA GEMM tiling: 128x128, 1-term: stage = A 16K + W 16K
#define MT 128
#define NT 128
#define NSTAGES 8
#define STAGE_BYTES 32768

// ---------------- scratch (device globals; no allocations) ----------------
__device__ __half g_v1h[(size_t)BB*AA*AA];   // 67 MB, fp16 v1 (+bias)
__device__ float g_spart[2*8*BA];
__device__ float g_w0[BA];
__device__ float g_w1[BA];
__device__ float g_hhred[2*BA];
__device__ float g_hhpart[4*2*BA];
__device__ float g_h2a1part[4*BA];
__device__ float g_sums4[4*BB*4096];
__device__ float g_nexth[BR];
__device__ float g_scores[BA];
__device__ float g_logits2[(size_t)2*BB*OUTN];
// fp16 operands
__device__ __half g_att_h[(size_t)BB*AA*RR];
__device__ __half g_w0_h[AA*RR];
__device__ __half g_w1_h[AA*RR];
__device__ __half g_h2aw_h[AA*RR];
__device__ __half g_h2a1w_h[AA*RR];
__device__ __half g_i2h_h[2*LW];
__device__ __half g_h2h_h[2*LW];
__device__ __half g_a2h_h[2*LW];
__device__ __half g_proj_hi[OUTN*RR];
__device__ __half g_proj_lo[OUTN*RR];
__device__ __half g_x_h[BR];
__device__ __half g_h01_h[2*BR];
__device__ __half g_xt_h[BR];
__device__ __half g_nh_h[BR];
__device__ __half g_th_h[BR];
__device__ __half g_ar_h[2*BR];

// ---------------- PTX helpers ----------------
__device__ __forceinline__ uint32_t smem_u32(const void* p){
    uint32_t a;
    asm("{ .reg .u64 t; cvta.to.shared.u64 t, %1; cvt.u32.u64 %0, t; }" : "=r"(a) : "l"(p));
    return a;
}
__device__ __forceinline__ void cp16(uint32_t dst, const void* src){
    asm volatile("cp.async.cg.shared.global [%0], [%1], 16;\n" :: "r"(dst), "l"(src));
}
__device__ __forceinline__ void cp16z(uint32_t dst, const void* src, bool ok){
    int sz = ok ? 16 : 0;
    asm volatile("cp.async.cg.shared.global [%0], [%1], 16, %2;\n" :: "r"(dst), "l"(src), "r"(sz));
}
#define CP_COMMIT()  asm volatile("cp.async.commit_group;\n" ::: "memory")
#define CP_WAIT0()   asm volatile("cp.async.wait_group 0;\n" ::: "memory")
#define CP_WAIT1()   asm volatile("cp.async.wait_group 1;\n" ::: "memory")

#define SWZ(off) ((off) ^ (((off) >> 3) & 0x70))

__device__ __forceinline__ void ldsm_x4(uint32_t& r0, uint32_t& r1, uint32_t& r2, uint32_t& r3, uint32_t addr){
    asm volatile("ldmatrix.sync.aligned.m8n8.x4.shared.b16 {%0,%1,%2,%3}, [%4];"
        : "=r"(r0), "=r"(r1), "=r"(r2), "=r"(r3) : "r"(addr));
}
__device__ __forceinline__ void mma16816(float* c, const uint32_t* a, const uint32_t* b){
    asm volatile(
        "mma.sync.aligned.m16n8k16.row.col.f32.f16.f16.f32 "
        "{%0,%1,%2,%3}, {%4,%5,%6,%7}, {%8,%9}, {%0,%1,%2,%3};"
        : "+f"(c[0]), "+f"(c[1]), "+f"(c[2]), "+f"(c[3])
        : "r"(a[0]), "r"(a[1]), "r"(a[2]), "r"(a[3]), "r"(b[0]), "r"(b[1]));
}

// ---------------- fp32 -> fp16 single (big arrays) ----------------
__global__ void tohalf_kernel(const float* __restrict__ in, __half* __restrict__ out, size_t n4)
{
    size_t i = (size_t)blockIdx.x*blockDim.x + threadIdx.x;
    if (i >= n4) return;
    float4 x = ((const float4*)in)[i];
    __half h[4] = { __float2half_rn(x.x), __float2half_rn(x.y),
                    __float2half_rn(x.z), __float2half_rn(x.w) };
    ((uint2*)out)[i] = *(uint2*)h;
}

// ---------------- fp32 -> fp16, up to 4 equal-size segments in one launch ----------------
__global__ void tohalf_multi_kernel(const float* __restrict__ s0, __half* __restrict__ d0,
                                    const float* __restrict__ s1, __half* __restrict__ d1,
                                    const float* __restrict__ s2, __half* __restrict__ d2,
                                    const float* __restrict__ s3, __half* __restrict__ d3,
                                    int nseg, size_t n4each)
{
    size_t gi = (size_t)blockIdx.x*blockDim.x + threadIdx.x;
    int seg = (int)(gi / n4each);
    if (seg >= nseg) return;
    size_t i = gi - (size_t)seg * n4each;
    const float* in = seg==0 ? s0 : seg==1 ? s1 : seg==2 ? s2 : s3;
    __half* out     = seg==0 ? d0 : seg==1 ? d1 : seg==2 ? d2 : d3;
    float4 x = ((const float4*)in)[i];
    __half h[4] = { __float2half_rn(x.x), __float2half_rn(x.y),
                    __float2half_rn(x.z), __float2half_rn(x.w) };
    ((uint2*)out)[i] = *(uint2*)h;
}

// ---------------- fp32 -> fp16 hi/lo split (proj only) ----------------
__global__ void splith_kernel(const float* __restrict__ in,
                              __half* __restrict__ hi, __half* __restrict__ lo, size_t n4)
{
    size_t i = (size_t)blockIdx.x*blockDim.x + threadIdx.x;
    if (i >= n4) return;
    float4 x = ((const float4*)in)[i];
    float xv[4] = {x.x, x.y, x.z, x.w};
    __half h[4], l[4];
    #pragma unroll
    for (int j=0;j<4;j++){
        h[j] = __float2half_rn(xv[j]);
        l[j] = __float2half_rn(xv[j] - __half2float(h[j]));
    }
    ((uint2*)hi)[i] = *(uint2*)h;
    ((uint2*)lo)[i] = *(uint2*)l;
}

// =====================================================================
// big HMMA fp16 1-term GEMM over att: C = att @ W^T  (round-9 version)
// =====================================================================
__global__ __launch_bounds__(256, 2)
void hmma_gemm_kernel(const __half* __restrict__ Ah,
                      const __half* __restrict__ W0h, const __half* __restrict__ W1h,
                      const float* __restrict__ ba0, const float* __restrict__ ba1,
                      const float* __restrict__ wd0,
                      const float* __restrict__ hh0, const float* __restrict__ hh1,
                      __half* __restrict__ v1out,
                      float* __restrict__ sp0, float* __restrict__ sp1)
{
    extern __shared__ char dsm[];
    const int tid  = threadIdx.x;
    const int wid  = tid >> 5;
    const int lane = tid & 31;
    const int grp  = lane >> 2;
    const int tid4 = lane & 3;
    const int set  = blockIdx.x & 1;
    const int nt4  = blockIdx.x >> 1;
    const int mBase = blockIdx.y * MT;
    const int nBase4 = nt4 * NT;
    const int wm = wid >> 1;
    const int wn = wid & 1;

    const __half* Wh = set ? W1h : W0h;
    const float* bias = set ? ba1 : ba0;

    const uint32_t sbase = smem_u32(dsm);

    const int l15 = lane & 15;
    const uint32_t Cx = ((uint32_t)(lane >> 4) * 16) ^ ((uint32_t)(lane & 7) << 4);
    const uint32_t offA0 = (uint32_t)(wm*32 + l15) * 128;
    const uint32_t offA1 = offA0 + 2048;
    uint32_t offB[4];
    #pragma unroll
    for (int p = 0; p < 4; p++) offB[p] = (uint32_t)(wn*64 + p*16 + l15) * 128;

    float acc[2][8][4];
    #pragma unroll
    for (int mt=0;mt<2;mt++)
        #pragma unroll
        for (int nt=0;nt<8;nt++)
            #pragma unroll
            for (int q=0;q<4;q++) acc[mt][nt][q]=0.f;

    auto load_stage = [&](int s){
        const uint32_t base = sbase + (s & 1) * STAGE_BYTES;
        const int kOff = s * 64;
        #pragma unroll
        for (int i = 0; i < 4; i++){
            int idx = tid + i * 256;
            int r = idx >> 3;
            int ch = idx & 7;
            const __half* src = Ah + (size_t)(mBase + r) * RR + kOff + ch * 8;
            cp16(base + SWZ(r * 128 + ch * 16), src);
        }
        #pragma unroll
        for (int i = 0; i < 4; i++){
            int idx = tid + i * 256;
            int r = idx >> 3;
            int ch = idx & 7;
            const __half* src = Wh + (size_t)(nBase4 + r) * RR + kOff + ch * 8;
            cp16(base + 16384 + SWZ(r * 128 + ch * 16), src);
        }
        CP_COMMIT();
    };

    load_stage(0);

    for (int s = 0; s < NSTAGES; s++){
        if (s + 1 < NSTAGES){ load_stage(s + 1); CP_WAIT1(); }
        else                 { CP_WAIT0(); }
        __syncthreads();

        const uint32_t sA = sbase + (s & 1) * STAGE_BYTES;
        const uint32_t sB = sA + 16384;
        #pragma unroll
        for (int k16 = 0; k16 < 4; k16++){
            const uint32_t ko = ((uint32_t)k16 * 32) ^ Cx;
            uint32_t a0[4], a1[4];
            ldsm_x4(a0[0], a0[1], a0[2], a0[3], sA + offA0 + ko);
            ldsm_x4(a1[0], a1[1], a1[2], a1[3], sA + offA1 + ko);
            #pragma unroll
            for (int p = 0; p < 4; p++){
                uint32_t b0, b1, b2, b3;
                ldsm_x4(b0, b1, b2, b3, sB + offB[p] + ko);
                uint32_t be[2] = {b0, b2};
                uint32_t bo[2] = {b1, b3};
                mma16816(acc[0][2*p],   a0, be);
                mma16816(acc[0][2*p+1], a0, bo);
                mma16816(acc[1][2*p],   a1, be);
                mma16816(acc[1][2*p+1], a1, bo);
            }
        }
        __syncthreads();
    }

    if (set == 1){
        #pragma unroll
        for (int mt = 0; mt < 2; mt++){
            #pragma unroll
            for (int rh = 0; rh < 2; rh++){
                int m = mBase + wm*32 + mt*16 + rh*8 + grp;
                __half* dst = v1out + (size_t)m * AA;
                #pragma unroll
                for (int nt = 0; nt < 8; nt++){
                    int n0 = nBase4 + wn*64 + nt*8 + tid4*2;
                    __half2 h2 = __floats2half2_rn(acc[mt][nt][rh*2+0] + bias[n0],
                                                   acc[mt][nt][rh*2+1] + bias[n0+1]);
                    *(__half2*)(dst + n0) = h2;
                }
            }
        }
    } else {
        const int part = nt4*2 + wn;
        #pragma unroll
        for (int mt = 0; mt < 2; mt++){
            #pragma unroll
            for (int rh = 0; rh < 2; rh++){
                int m = mBase + wm*32 + mt*16 + rh*8 + grp;
                float h0 = hh0[m], h1 = hh1[m];
                float p0 = 0.f, p1 = 0.f;
                #pragma unroll
                for (int nt = 0; nt < 8; nt++){
                    int n0 = nBase4 + wn*64 + nt*8 + tid4*2;
                    float v0 = acc[mt][nt][rh*2+0] + bias[n0];
                    float v1v = acc[mt][nt][rh*2+1] + bias[n0+1];
                    float wv0 = wd0[n0], wv1 = wd0[n0+1];
                    p0 += tanhf(v0 + h0)*wv0 + tanhf(v1v + h0)*wv1;
                    p1 += tanhf(v0 + h1)*wv0 + tanhf(v1v + h1)*wv1;
                }
                p0 += __shfl_down_sync(0xffffffffu, p0, 2, 4);
                p0 += __shfl_down_sync(0xffffffffu, p0, 1, 4);
                p1 += __shfl_down_sync(0xffffffffu, p1, 2, 4);
                p1 += __shfl_down_sync(0xffffffffu, p1, 1, 4);
                if (tid4 == 0){
                    sp0[(size_t)part*BA + m] = p0;
                    sp1[(size_t)part*BA + m] = p1;
                }
            }
        }
    }
}

// =====================================================================
// Generic fp16 GEMM, 128x64 tile, multi-source K, K-split (round-9 version)
// =====================================================================
template<int NSRC, bool TWOTERM>
__global__ __launch_bounds__(256, 2)
void hgemm_kernel(const __half* __restrict__ Xh0,
                  const __half* __restrict__ Whi0, const __half* __restrict__ Wlo0,
                  const __half* __restrict__ Xh1,
                  const __half* __restrict__ Whi1, const __half* __restrict__ Wlo1,
                  const __half* __restrict__ Xh2,
                  const __half* __restrict__ Whi2, const __half* __restrict__ Wlo2,
                  float* __restrict__ out, int Nreal, int kStride)
{
    constexpr uint32_t STG = TWOTERM ? 32768 : 24576;
    extern __shared__ char dsm[];
    const int tid  = threadIdx.x;
    const int wid  = tid >> 5;
    const int lane = tid & 31;
    const int grp  = lane >> 2;
    const int tid4 = lane & 3;
    const int nBase = blockIdx.x * 64;
    const int kIdx  = blockIdx.y;
    const int mBase = blockIdx.z * 128;
    const int wm = wid >> 1;
    const int wn = wid & 1;
    const uint32_t sbase = smem_u32(dsm);

    const int spc  = (NSRC * 8) / gridDim.y;
    const int sBeg = kIdx * spc;

    const int l15 = lane & 15;
    const uint32_t Cx = ((uint32_t)(lane >> 4) * 16) ^ ((uint32_t)(lane & 7) << 4);
    const uint32_t offA0 = (uint32_t)(wm*32 + l15) * 128;
    const uint32_t offA1 = offA0 + 2048;
    uint32_t offB[2];
    #pragma unroll
    for (int p = 0; p < 2; p++) offB[p] = (uint32_t)(wn*32 + p*16 + l15) * 128;

    float acc[2][4][4];
    #pragma unroll
    for (int mt=0;mt<2;mt++)
        #pragma unroll
        for (int nt=0;nt<4;nt++)
            #pragma unroll
            for (int q=0;q<4;q++) acc[mt][nt][q]=0.f;

    auto load_stage = [&](int s, int buf){
        const uint32_t base = sbase + buf * STG;
        const int src = s >> 3;
        const int kOff = (s & 7) * 64;
        const __half *xh, *wh, *wl;
        if (NSRC == 1 || src == 0){ xh=Xh0; wh=Whi0; wl=Wlo0; }
        else if (src == 1){ xh=Xh1; wh=Whi1; wl=Wlo1; }
        else { xh=Xh2; wh=Whi2; wl=Wlo2; }
        #pragma unroll
        for (int i = 0; i < 4; i++){
            int idx = tid + i * 256;
            int r = idx >> 3;
            int ch = idx & 7;
            const __half* src_p = xh + (size_t)(mBase + r) * 512 + kOff + ch * 8;
            cp16(base + SWZ(r * 128 + ch * 16), src_p);
        }
        #pragma unroll
        for (int i = 0; i < (TWOTERM ? 4 : 2); i++){
            int idx = tid + i * 256;
            int half = idx >> 9;
            int r = (idx >> 3) & 63;
            int ch = idx & 7;
            bool ok = (nBase + r) < Nreal;
            const __half* src_p = ((TWOTERM && half) ? wl : wh) + (size_t)(nBase + r) * 512 + kOff + ch * 8;
            cp16z(base + 16384 + half * 8192 + SWZ(r * 128 + ch * 16), src_p, ok);
        }
        CP_COMMIT();
    };

    load_stage(sBeg, 0);

    for (int i = 0; i < spc; i++){
        if (i + 1 < spc){ load_stage(sBeg + i + 1, (i + 1) & 1); CP_WAIT1(); }
        else            { CP_WAIT0(); }
        __syncthreads();

        const uint32_t sA  = sbase + (i & 1) * STG;
        const uint32_t sBh = sA + 16384;
        const uint32_t sBl = sA + 24576;
        #pragma unroll
        for (int k16 = 0; k16 < 4; k16++){
            const uint32_t ko = ((uint32_t)k16 * 32) ^ Cx;
            uint32_t a0[4], a1[4];
            ldsm_x4(a0[0], a0[1], a0[2], a0[3], sA + offA0 + ko);
            ldsm_x4(a1[0], a1[1], a1[2], a1[3], sA + offA1 + ko);
            #pragma unroll
            for (int p = 0; p < 2; p++){
                uint32_t b0, b1, b2, b3;
                ldsm_x4(b0, b1, b2, b3, sBh + offB[p] + ko);
                uint32_t be[2] = {b0, b2};
                uint32_t bo[2] = {b1, b3};
                mma16816(acc[0][2*p],   a0, be);
                mma16816(acc[0][2*p+1], a0, bo);
                mma16816(acc[1][2*p],   a1, be);
                mma16816(acc[1][2*p+1], a1, bo);
                if (TWOTERM){
                    ldsm_x4(b0, b1, b2, b3, sBl + offB[p] + ko);
                    uint32_t ce[2] = {b0, b2};
                    uint32_t co[2] = {b1, b3};
                    mma16816(acc[0][2*p],   a0, ce);
                    mma16816(acc[0][2*p+1], a0, co);
                    mma16816(acc[1][2*p],   a1, ce);
                    mma16816(acc[1][2*p+1], a1, co);
                }
            }
        }
        __syncthreads();
    }

    float* obase = out + (size_t)kIdx * kStride;
    #pragma unroll
    for (int mt = 0; mt < 2; mt++){
        #pragma unroll
        for (int rh = 0; rh < 2; rh++){
            int m = mBase + wm*32 + mt*16 + rh*8 + grp;
            #pragma unroll
            for (int nt = 0; nt < 4; nt++){
                int n0 = nBase + wn*32 + nt*8 + tid4*2;
                if (n0 < Nreal){
                    float2 v2;
                    v2.x = acc[mt][nt][rh*2+0];
                    v2.y = acc[mt][nt][rh*2+1];
                    *(float2*)(obase + (size_t)m * Nreal + n0) = v2;
                }
            }
        }
    }
}

// ---------------- reduce partials + bias (biasN=512) ----------------
__global__ void reduce_bias_kernel(const float* __restrict__ in, const float* __restrict__ bias,
                                   float* __restrict__ out, int n, int parts, int pstride)
{
    int i = blockIdx.x*256 + threadIdx.x;
    if (i >= n) return;
    float s = bias[i & 511];
    for (int p = 0; p < parts; p++) s += in[(size_t)p*pstride + i];
    out[i] = s;
}

// ---------------- softmax over a (A=512), summing nparts partials ----------------
__global__ void softmax512_kernel(const float* __restrict__ in, float* __restrict__ out, int nparts)
{
    __shared__ float sm[8];
    int b = blockIdx.x, t = threadIdx.x;
    float v0=0.f, v1=0.f;
    for (int p=0;p<nparts;p++){
        const float* ip = in + (size_t)p*BA + (size_t)b*AA;
        v0 += ip[t]; v1 += ip[t+256];
    }
    float m = fmaxf(v0,v1);
    for (int o=16;o;o>>=1) m = fmaxf(m, __shfl_xor_sync(0xffffffffu,m,o));
    if ((t&31)==0) sm[t>>5]=m;
    __syncthreads();
    float M = sm[0];
    #pragma unroll
    for (int i=1;i<8;i++) M = fmaxf(M, sm[i]);
    __syncthreads();
    float e0=expf(v0-M), e1=expf(v1-M);
    float s = e0+e1;
    for (int o=16;o;o>>=1) s += __shfl_xor_sync(0xffffffffu,s,o);
    if ((t&31)==0) sm[t>>5]=s;
    __syncthreads();
    float S=0.f;
    #pragma unroll
    for (int i=0;i<8;i++) S += sm[i];
    float inv = 1.f/S;
    out[(size_t)b*AA + t]     = e0*inv;
    out[(size_t)b*AA + t+256] = e1*inv;
}

// ---------------- score scan over fp16 v1, fusing h2a1 partial-reduce ----------------
__global__ void v1_scores_kernel(const __half* __restrict__ v1, const float* __restrict__ parts,
                                 const float* __restrict__ hbias,
                                 const float* __restrict__ wd, float* __restrict__ scores)
{
    __shared__ float sm[4];
    int a = blockIdx.x, b = blockIdx.y, t = threadIdx.x;   // 128 threads
    size_t hidx = (size_t)b*AA + a;
    float h = hbias[a];
    #pragma unroll
    for (int p=0;p<4;p++) h += parts[(size_t)p*BA + hidx];
    uint2 u = ((const uint2*)(v1 + hidx*AA))[t];
    float2 f01 = __half22float2(*reinterpret_cast<__half2*>(&u.x));
    float2 f23 = __half22float2(*reinterpret_cast<__half2*>(&u.y));
    float4 w = ((const float4*)wd)[t];
    float s = tanhf(f01.x+h)*w.x + tanhf(f01.y+h)*w.y + tanhf(f23.x+h)*w.z + tanhf(f23.y+h)*w.w;
    for (int o=16;o;o>>=1) s += __shfl_xor_sync(0xffffffffu,s,o);
    if ((t&31)==0) sm[t>>5]=s;
    __syncthreads();
    if (t==0) scores[hidx] = sm[0]+sm[1]+sm[2]+sm[3];
}

// ---------------- att_res over fp16 att (+ fused fp16 converts) ----------------
template<bool DUAL, bool ADD>
__global__ void attres_kernel(const __half* __restrict__ att,
                              const float* __restrict__ w0, const float* __restrict__ w1,
                              const float* __restrict__ addv, const float* __restrict__ xadd,
                              float* __restrict__ out0,
                              __half* __restrict__ h0out, __half* __restrict__ h1out)
{
    __shared__ float sw0[AA];
    __shared__ float sw1[AA];
    int b = blockIdx.y;
    int r = blockIdx.x*256 + threadIdx.x;
    for (int a=threadIdx.x; a<AA; a+=256){
        sw0[a]=w0[(size_t)b*AA+a];
        if (DUAL) sw1[a]=w1[(size_t)b*AA+a];
    }
    __syncthreads();
    float acc0=0.f, acc1=0.f;
    const __half* ap = att + (size_t)b*AA*RR + r;
    #pragma unroll 8
    for (int a=0;a<AA;a++){
        float av = __half2float(ap[(size_t)a*RR]);
        acc0 = fmaf(sw0[a], av, acc0);
        if (DUAL) acc1 = fmaf(sw1[a], av, acc1);
    }
    size_t idx = (size_t)b*RR + r;
    if (ADD) acc0 += addv[idx];
    if (out0) out0[idx] = acc0;
    float e0 = xadd ? acc0 + xadd[idx] : acc0;
    h0out[idx] = __float2half_rn(e0);
    if (DUAL) h1out[idx] = __float2half_rn(acc1);
}

// ---------------- LSTM pointwise: sums 4 K-split partials + biases ----------------
__global__ void lstm_pw_kernel(const float* __restrict__ sums4,
                               const float* __restrict__ bi, const float* __restrict__ bh,
                               const float* __restrict__ ba,
                               const float* __restrict__ prev_c,
                               float* __restrict__ next_c, float* __restrict__ next_h,
                               __half* __restrict__ nh_h)
{
    int idx = blockIdx.x*256 + threadIdx.x;
    int b = idx >> 9, r = idx & 511;
    float pc = prev_c[idx];
    float cs=0.f, hs=0.f;
    #pragma unroll
    for (int p=0;p<2;p++){
        float g[4];
        #pragma unroll
        for (int gi=0; gi<4; gi++){
            int off = p*2048 + gi*512 + r;
            float s = bi[off] + bh[off] + ba[off];
            #pragma unroll
            for (int q=0;q<4;q++) s += sums4[(size_t)q*(BB*4096) + (size_t)b*4096 + off];
            g[gi] = s;
        }
        float ig = 1.f/(1.f+expf(-g[0]));
        float fg = 1.f/(1.f+expf(-g[1]));
        float og = 1.f/(1.f+expf(-g[2]));
        float tt = tanhf(g[3]);
        float c  = fg*pc + ig*tt;
        cs += c; hs += og*tanhf(c);
    }
    float nc = cs*0.5f, nh = hs*0.5f;
    next_c[idx] = nc;
    next_h[idx] = nh;
    nh_h[idx] = __float2half_rn(nh);
}

// ---------------- log_softmax: sums 2 proj partials + bias, smem-cached ----------------
__global__ void logsoftmax_kernel(const float* __restrict__ parts, const float* __restrict__ bias,
                                  float* __restrict__ out)
{
    __shared__ float sx[OUTN];
    __shared__ float sm[8];
    int b = blockIdx.x, t = threadIdx.x;
    const float* a0 = parts + (size_t)b*OUTN;
    const float* a1 = parts + (size_t)(BB + b)*OUTN;
    for (int i=t;i<OUTN;i+=256) sx[i] = a0[i] + a1[i] + bias[i];
    __syncthreads();
    float m = -3.4e38f;
    for (int i=t;i<OUTN;i+=256) m = fmaxf(m, sx[i]);
    for (int o=16;o;o>>=1) m = fmaxf(m, __shfl_xor_sync(0xffffffffu,m,o));
    if ((t&31)==0) sm[t>>5]=m;
    __syncthreads();
    float M = sm[0];
    #pragma unroll
    for (int i=1;i<8;i++) M = fmaxf(M, sm[i]);
    __syncthreads();
    float s=0.f;
    for (int i=t;i<OUTN;i+=256) s += expf(sx[i]-M);
    for (int o=16;o;o>>=1) s += __shfl_xor_sync(0xffffffffu,s,o);
    if ((t&31)==0) sm[t>>5]=s;
    __syncthreads();
    float S=0.f;
    #pragma unroll
    for (int i=0;i<8;i++) S += sm[i];
    float L = M + logf(S);
    for (int i=t;i<OUTN;i+=256) out[(size_t)b*OUTN+i] = sx[i]-L;
}

// =====================================================================
extern "C" void kernel_launch(void* const* d_in, const int* in_sizes, int n_in,
                              void* d_out, int out_size)
{
    const float* x      = (const float*)d_in[0];
    const float* att    = (const float*)d_in[1];
    const float* inputs = (const float*)d_in[2];
    const float* a2a_w  = (const float*)d_in[3];
    const float* a2a_b  = (const float*)d_in[4];
    const float* h2a_w  = (const float*)d_in[5];
    const float* h2a_b  = (const float*)d_in[6];
    const float* d2d_w  = (const float*)d_in[7];
    const float* a2a1_w = (const float*)d_in[9];
    const float* a2a1_b = (const float*)d_in[10];
    const float* h2a1_w = (const float*)d_in[11];
    const float* h2a1_b = (const float*)d_in[12];
    const float* d2d1_w = (const float*)d_in[13];
    const float* i2h_w  = (const float*)d_in[15];
    const float* i2h_b  = (const float*)d_in[16];
    const float* h2h_w  = (const float*)d_in[17];
    const float* h2h_b  = (const float*)d_in[18];
    const float* a2h_w  = (const float*)d_in[19];
    const float* a2h_b  = (const float*)d_in[20];
    const float* proj_w = (const float*)d_in[21];
    const float* proj_b = (const float*)d_in[22];
    float* out = (float*)d_out;

    float *spart, *w0p, *w1p, *hhredp, *hhpartp, *h2a1partp, *sums4p, *nexthp, *scoresp, *logits2p;
    __half* v1hp;
    cudaGetSymbolAddress((void**)&v1hp,     g_v1h);
    cudaGetSymbolAddress((void**)&spart,    g_spart);
    cudaGetSymbolAddress((void**)&w0p,      g_w0);
    cudaGetSymbolAddress((void**)&w1p,      g_w1);
    cudaGetSymbolAddress((void**)&hhredp,   g_hhred);
    cudaGetSymbolAddress((void**)&hhpartp,  g_hhpart);
    cudaGetSymbolAddress((void**)&h2a1partp,g_h2a1part);
    cudaGetSymbolAddress((void**)&sums4p,   g_sums4);
    cudaGetSymbolAddress((void**)&nexthp,   g_nexth);
    cudaGetSymbolAddress((void**)&scoresp,  g_scores);
    cudaGetSymbolAddress((void**)&logits2p, g_logits2);

    __half *ah,*w0h,*w1h,*h2awh,*h2a1wh,*i2hh,*h2hh,*a2hh,*projhi,*projlo;
    __half *xh,*h01h,*xth,*nhh,*thh,*arh;
    cudaGetSymbolAddress((void**)&ah, g_att_h);
    cudaGetSymbolAddress((void**)&w0h, g_w0_h);
    cudaGetSymbolAddress((void**)&w1h, g_w1_h);
    cudaGetSymbolAddress((void**)&h2awh, g_h2aw_h);
    cudaGetSymbolAddress((void**)&h2a1wh, g_h2a1w_h);
    cudaGetSymbolAddress((void**)&i2hh, g_i2h_h);
    cudaGetSymbolAddress((void**)&h2hh, g_h2h_h);
    cudaGetSymbolAddress((void**)&a2hh, g_a2h_h);
    cudaGetSymbolAddress((void**)&projhi, g_proj_hi);
    cudaGetSymbolAddress((void**)&projlo, g_proj_lo);
    cudaGetSymbolAddress((void**)&xh, g_x_h);
    cudaGetSymbolAddress((void**)&h01h, g_h01_h);
    cudaGetSymbolAddress((void**)&xth, g_xt_h);
    cudaGetSymbolAddress((void**)&nhh, g_nh_h);
    cudaGetSymbolAddress((void**)&thh, g_th_h);
    cudaGetSymbolAddress((void**)&arh, g_ar_h);

    const float* prev_c0 = inputs;
    const float* prev_h0 = inputs + 1*BR;
    const float* prev_c1 = inputs + 2*BR;
    const float* prev_h1 = inputs + 3*BR;

    float* sp0 = spart;
    float* sp1 = spart + (size_t)8*BA;

    cudaFuncSetAttribute(hmma_gemm_kernel, cudaFuncAttributeMaxDynamicSharedMemorySize, 2*STAGE_BYTES);
    cudaFuncSetAttribute((hgemm_kernel<1,false>), cudaFuncAttributeMaxDynamicSharedMemorySize, 2*24576);
    cudaFuncSetAttribute((hgemm_kernel<3,false>), cudaFuncAttributeMaxDynamicSharedMemorySize, 2*24576);
    cudaFuncSetAttribute((hgemm_kernel<1,true>),  cudaFuncAttributeMaxDynamicSharedMemorySize, 2*32768);

    // ---- side streams + events (created once, on the uncaptured correctness call) ----
    static cudaStream_t strB = nullptr, strC = nullptr;
    static cudaEvent_t evFork = nullptr, evB = nullptr, evC = nullptr;
    if (strB == nullptr){
        cudaStreamCreateWithFlags(&strB, cudaStreamNonBlocking);
        cudaStreamCreateWithFlags(&strC, cudaStreamNonBlocking);
        cudaEventCreateWithFlags(&evFork, cudaEventDisableTiming);
        cudaEventCreateWithFlags(&evB,    cudaEventDisableTiming);
        cudaEventCreateWithFlags(&evC,    cudaEventDisableTiming);
    }

    // fork
    cudaEventRecord(evFork, 0);
    cudaStreamWaitEvent(strB, evFork, 0);
    cudaStreamWaitEvent(strC, evFork, 0);

    // ---- stream B: attn weights + activations -> hh GEMM chain ----
    tohalf_multi_kernel<<<(4*65536+255)/256,256,0,strB>>>(
        a2a_w, w0h, a2a1_w, w1h, h2a_w, h2awh, h2a1_w, h2a1wh, 4, 65536);
    tohalf_multi_kernel<<<(3*16384+255)/256,256,0,strB>>>(
        x, xh, prev_h0, h01h, prev_h1, h01h+BR, 0, 0, 3, 16384);
    hgemm_kernel<1,false><<<dim3(8,4,2),256,2*24576,strB>>>(
        h01h, h2awh, 0, 0,0,0, 0,0,0, hhpartp, AA, 2*BA);
    reduce_bias_kernel<<<(2*BA+255)/256,256,0,strB>>>(hhpartp, h2a_b, hhredp, 2*BA, 4, 2*BA);
    cudaEventRecord(evB, strB);

    // ---- stream C: LSTM weights + proj split (needed only after the big GEMM) ----
    tohalf_multi_kernel<<<(3*1048576+255)/256,256,0,strC>>>(
        i2h_w, i2hh, h2h_w, h2hh, a2h_w, a2hh, 0, 0, 3, 1048576);
    splith_kernel<<<5000,256,0,strC>>>(proj_w, projhi, projlo, OUTN*RR/4);
    cudaEventRecord(evC, strC);

    // ---- stream 0: att convert (gates big GEMM) ----
    {
        size_t n4 = (size_t)BB*AA*RR/4;
        tohalf_kernel<<<(unsigned)((n4+255)/256),256>>>(att, ah, n4);
    }
    cudaStreamWaitEvent(0, evB, 0);

    // ---- big tensor GEMMs ----
    hmma_gemm_kernel<<<dim3(8,512),256,2*STAGE_BYTES>>>(
        ah, w0h, w1h, a2a_b, a2a1_b, d2d_w, hhredp, hhredp+BA, v1hp, sp0, sp1);

    softmax512_kernel<<<BB,256>>>(sp0, w0p, 8);
    softmax512_kernel<<<BB,256>>>(sp1, w1p, 8);

    // both prev att_res (fp16 att source)
    attres_kernel<true,false><<<dim3(2,BB),256>>>(ah, w0p, w1p, nullptr, nullptr,
        nullptr, arh, arh+BR);

    cudaStreamWaitEvent(0, evC, 0);   // LSTM weights + proj split joined

    // ---- layer 0 ----
    hgemm_kernel<3,false><<<dim3(64,4,1),256,2*24576>>>(
        xh, i2hh, 0,
        h01h, h2hh, 0,
        arh, a2hh, 0,
        sums4p, 4096, BB*4096);
    lstm_pw_kernel<<<BR/256,256>>>(sums4p, i2h_b, h2h_b, a2h_b, prev_c0,
                                   out + 0, nexthp, nhh);

    hgemm_kernel<1,false><<<dim3(8,4,1),256,2*24576>>>(
        nhh, h2a1wh, 0, 0,0,0, 0,0,0, h2a1partp, AA, BA);
    v1_scores_kernel<<<dim3(AA,BB),128>>>(v1hp, h2a1partp, h2a1_b, d2d1_w, scoresp);
    softmax512_kernel<<<BB,256>>>(scoresp, w0p, 1);
    // top_h0 -> out+BR; xt = x + top_h0 -> fp16
    attres_kernel<false,true><<<dim3(2,BB),256>>>(ah, w0p, nullptr, nexthp, x,
        out + BR, xth, nullptr);

    // ---- layer 1 ----
    hgemm_kernel<3,false><<<dim3(64,4,1),256,2*24576>>>(
        xth, i2hh + LW, 0,
        h01h + BR, h2hh + LW, 0,
        arh + BR, a2hh + LW, 0,
        sums4p, 4096, BB*4096);
    lstm_pw_kernel<<<BR/256,256>>>(sums4p, i2h_b + LB, h2h_b + LB, a2h_b + LB, prev_c1,
                                   out + 2*BR, nexthp, nhh);

    hgemm_kernel<1,false><<<dim3(8,4,1),256,2*24576>>>(
        nhh, h2a1wh, 0, 0,0,0, 0,0,0, h2a1partp, AA, BA);
    v1_scores_kernel<<<dim3(AA,BB),128>>>(v1hp, h2a1partp, h2a1_b, d2d1_w, scoresp);
    softmax512_kernel<<<BB,256>>>(scoresp, w0p, 1);
    // top_h1 -> out+3BR and fp16 for proj
    attres_kernel<false,true><<<dim3(2,BB),256>>>(ah, w0p, nullptr, nexthp, nullptr,
        out + 3*BR, thh, nullptr);

    // ---- projection + log_softmax (2-term: logits are output-critical) ----
    hgemm_kernel<1,true><<<dim3(157,2,1),256,2*32768>>>(
        thh, projhi, projlo, 0,0,0, 0,0,0, logits2p, OUTN, BB*OUTN);
    logsoftmax_kernel<<<BB,256>>>(logits2p, proj_b, out + 4*BR);
}